// round 4
// baseline (speedup 1.0000x reference)
#include <cuda_runtime.h>
#include <cuda_bf16.h>

#define BB 1024
#define CC 1000
#define HH 512
#define NEG_INF (__int_as_float(0xff800000))

__device__ float g_G[1024 * 1024];   // full symmetric Gram, 4MB
__device__ float g_norm[1024];       // diagonal of G
__device__ float g_ymax[BB];
__device__ int   g_jmax[BB];

typedef unsigned long long ull;

__device__ __forceinline__ void fma2(ull& acc, ull a, ull b) {
    asm("fma.rn.f32x2 %0, %1, %2, %0;" : "+l"(acc) : "l"(a), "l"(b));
}
__device__ __forceinline__ float lo32(ull u) { return __uint_as_float((unsigned)u); }
__device__ __forceinline__ float hi32(ull u) { return __uint_as_float((unsigned)(u >> 32)); }

// ---------------------------------------------------------------------------
// K1 fused: bid < 136  -> Gram 64x64 upper-tri tile (FMA-bound)
//           bid >= 136 -> one y-row: argmax/max + copy into out (DRAM-bound)
// The two populations overlap: gram saturates the fma pipe while copy blocks
// saturate HBM.
// ---------------------------------------------------------------------------
#define NT 16
#define NGRAM (NT * (NT + 1) / 2)   // 136
#define BK 32
#define NKS (HH / BK)               // 16
#define SROW 34                     // even stride; 34 mod 32 = 2 -> conflict-free

__global__ void __launch_bounds__(128)
k_main(const float* __restrict__ y,
       const float* __restrict__ w,
       float* __restrict__ out) {
    __shared__ float As[64 * SROW];
    __shared__ float Bs[64 * SROW];
    const int t = threadIdx.x;

    if (blockIdx.x >= NGRAM) {
        // ---------------- argmax + copy: one y-row per block ----------------
        // NOTE: out rows have stride 1001 floats -> odd rows are NOT 16B
        // aligned; stores must stay scalar. Loads from y (stride 1000) are
        // float4-aligned.
        const int b = blockIdx.x - NGRAM;
        const float4* yr = (const float4*)(y + (long)b * CC);
        float* orow = out + (long)b * (CC + 1);

        float vmax = NEG_INF; int imax = 0;
        #pragma unroll
        for (int r = 0; r < 2; r++) {
            const int i = t + 128 * r;
            if (i < CC / 4) {
                const float4 v = __ldg(&yr[i]);
                const int c = i * 4;
                orow[c] = v.x; orow[c + 1] = v.y; orow[c + 2] = v.z; orow[c + 3] = v.w;
                if (v.x > vmax) { vmax = v.x; imax = c; }
                if (v.y > vmax) { vmax = v.y; imax = c + 1; }
                if (v.z > vmax) { vmax = v.z; imax = c + 2; }
                if (v.w > vmax) { vmax = v.w; imax = c + 3; }
            }
        }
        const int lane = t & 31, wid = t >> 5;
        #pragma unroll
        for (int o = 16; o > 0; o >>= 1) {
            const float v2 = __shfl_xor_sync(0xffffffffu, vmax, o);
            const int   i2 = __shfl_xor_sync(0xffffffffu, imax, o);
            if (v2 > vmax || (v2 == vmax && i2 < imax)) { vmax = v2; imax = i2; }
        }
        float* swv = As;                     // reuse smem
        int*   swi = (int*)Bs;
        if (lane == 0) { swv[wid] = vmax; swi[wid] = imax; }
        __syncthreads();
        if (t == 0) {
            float bv = swv[0]; int bi = swi[0];
            #pragma unroll
            for (int k = 1; k < 4; k++) {
                if (swv[k] > bv || (swv[k] == bv && swi[k] < bi)) { bv = swv[k]; bi = swi[k]; }
            }
            g_ymax[b] = bv; g_jmax[b] = bi;
        }
        return;
    }

    // -------------------------- Gram tile --------------------------
    int p = blockIdx.x;
    int ti = 0;
    while (p >= NT - ti) { p -= NT - ti; ti++; }
    const int tj = ti + p;

    const int lrow = t >> 3;        // 0..15
    const int seg  = t & 7;         // 0..7
    const int tr8  = (t >> 4) * 8;  // 0..56
    const int tc   = t & 15;

    const float* pA[4];
    const float* pB[4];
    #pragma unroll
    for (int m = 0; m < 4; m++) {
        const int ra = min(ti * 64 + lrow + 16 * m, CC - 1);
        const int rb = min(tj * 64 + lrow + 16 * m, CC - 1);
        pA[m] = w + (long)ra * HH + seg * 4;
        pB[m] = w + (long)rb * HH + seg * 4;
    }

    ull acc[8][4];
    #pragma unroll
    for (int i = 0; i < 8; i++)
        #pragma unroll
        for (int g = 0; g < 4; g++) acc[i][g] = 0ull;

    float4 ra4[4], rb4[4];
    #pragma unroll
    for (int m = 0; m < 4; m++) {
        ra4[m] = *(const float4*)(pA[m]);
        rb4[m] = *(const float4*)(pB[m]);
    }

    #pragma unroll 1
    for (int ks = 0; ks < NKS; ks++) {
        __syncthreads();
        #pragma unroll
        for (int m = 0; m < 4; m++) {
            const int base = (lrow + 16 * m) * SROW + seg * 4;
            *(float2*)&As[base]     = make_float2(ra4[m].x, ra4[m].y);
            *(float2*)&As[base + 2] = make_float2(ra4[m].z, ra4[m].w);
            *(float2*)&Bs[base]     = make_float2(rb4[m].x, rb4[m].y);
            *(float2*)&Bs[base + 2] = make_float2(rb4[m].z, rb4[m].w);
        }
        __syncthreads();

        if (ks + 1 < NKS) {                    // prefetch next K-slab
            const int off = (ks + 1) * BK;
            #pragma unroll
            for (int m = 0; m < 4; m++) {
                ra4[m] = *(const float4*)(pA[m] + off);
                rb4[m] = *(const float4*)(pB[m] + off);
            }
        }

        #pragma unroll
        for (int kk = 0; kk < BK / 2; kk++) {
            ull a[8], b[4];
            #pragma unroll
            for (int i = 0; i < 8; i++)
                a[i] = *(const ull*)&As[(tr8 + i) * SROW + 2 * kk];
            #pragma unroll
            for (int g = 0; g < 4; g++)
                b[g] = *(const ull*)&Bs[(tc + 16 * g) * SROW + 2 * kk];
            #pragma unroll
            for (int i = 0; i < 8; i++)
                #pragma unroll
                for (int g = 0; g < 4; g++)
                    fma2(acc[i][g], a[i], b[g]);
        }
    }

    float res[8][4];
    #pragma unroll
    for (int i = 0; i < 8; i++)
        #pragma unroll
        for (int g = 0; g < 4; g++)
            res[i][g] = lo32(acc[i][g]) + hi32(acc[i][g]);

    const int gr = ti * 64 + tr8;
    const int gc = tj * 64 + tc;
    #pragma unroll
    for (int i = 0; i < 8; i++)
        #pragma unroll
        for (int g = 0; g < 4; g++)
            g_G[(long)(gr + i) * 1024 + gc + 16 * g] = res[i][g];
    // mirror store: float4 down rows; diagonal tiles double-write identical
    // values (benign).
    #pragma unroll
    for (int g = 0; g < 4; g++) {
        const long mrow = (long)(gc + 16 * g) * 1024;
        float4 v0, v1;
        v0.x = res[0][g]; v0.y = res[1][g]; v0.z = res[2][g]; v0.w = res[3][g];
        v1.x = res[4][g]; v1.y = res[5][g]; v1.z = res[6][g]; v1.w = res[7][g];
        *(float4*)&g_G[mrow + gr]     = v0;
        *(float4*)&g_G[mrow + gr + 4] = v1;
    }
    if (ti == tj) {   // free norms: diagonal of G
        #pragma unroll
        for (int i = 0; i < 8; i++)
            #pragma unroll
            for (int g = 0; g < 4; g++)
                if (tr8 + i == tc + 16 * g)
                    g_norm[ti * 64 + tr8 + i] = res[i][g];
    }
}

// ---------------------------------------------------------------------------
// K2: y_bot. warp-per-row; loads batched up-front (MLP ~24), pruned sqrt.
// ---------------------------------------------------------------------------
__global__ void k_bot(const float* __restrict__ y,
                      const float* __restrict__ eps_p,
                      const float* __restrict__ lip_p,
                      float* __restrict__ out) {
    const int b    = (blockIdx.x * blockDim.x + threadIdx.x) >> 5;
    const int lane = threadIdx.x & 31;
    if (b >= BB) return;

    const float s  = (*eps_p) * fabsf(*lip_p);
    const float s2 = s * s;

    const int   j    = g_jmax[b];
    const float ymax = g_ymax[b];
    const float nj   = g_norm[j];
    const float4* yr = (const float4*)(y + (long)b * CC);
    const float4* gr = (const float4*)(g_G + (long)j * 1024);
    const float4* nr = (const float4*)g_norm;

    float4 vy[8], vg[8], vn[8];
    #pragma unroll
    for (int k = 0; k < 8; k++) {
        const int i = lane + 32 * k;
        if (i < CC / 4) {
            vy[k] = __ldg(&yr[i]);
            vg[k] = gr[i];
            vn[k] = nr[i];
        }
    }

    float best = NEG_INF;
    #pragma unroll
    for (int k = 0; k < 8; k++) {
        const int i = lane + 32 * k;
        if (i >= CC / 4) break;
        #pragma unroll
        for (int e = 0; e < 4; e++) {
            const float yve = (e == 0) ? vy[k].x : (e == 1) ? vy[k].y : (e == 2) ? vy[k].z : vy[k].w;
            const float gve = (e == 0) ? vg[k].x : (e == 1) ? vg[k].y : (e == 2) ? vg[k].z : vg[k].w;
            const float nve = (e == 0) ? vn[k].x : (e == 1) ? vn[k].y : (e == 2) ? vn[k].z : vn[k].w;
            if (yve == ymax) continue;           // ref masks y==ymax -> -inf
            float sq = fmaf(-2.f, gve, nj + nve);
            if (sq < 0.f) sq = 0.f;
            const float d = best - yve;
            if (d <= 0.f || sq * s2 > d * d) {   // not provably <= best
                best = fmaxf(best, fmaf(s, sqrtf(sq), yve));
            }
        }
    }
    #pragma unroll
    for (int o = 16; o > 0; o >>= 1)
        best = fmaxf(best, __shfl_xor_sync(0xffffffffu, best, o));
    if (lane == 0) out[(long)b * (CC + 1) + CC] = best;
}

// ---------------------------------------------------------------------------
extern "C" void kernel_launch(void* const* d_in, const int* in_sizes, int n_in,
                              void* d_out, int out_size) {
    const float* y   = (const float*)d_in[0];
    const float* w   = (const float*)d_in[1];
    const float* eps = (const float*)d_in[2];
    const float* lip = (const float*)d_in[3];
    float* out = (float*)d_out;

    k_main<<<NGRAM + BB, 128>>>(y, w, out);
    k_bot<<<(32 * BB + 255) / 256, 256>>>(y, eps, lip, out);
}

// round 5
// speedup vs baseline: 1.2614x; 1.2614x over previous
#include <cuda_runtime.h>
#include <cuda_bf16.h>

#define BB 1024
#define CC 1000
#define HH 512
#define NEG_INF (__int_as_float(0xff800000))

__device__ float g_G2[2][1024 * 1024];   // split-K Gram partials, 8MB
__device__ float g_norm2[2][1024];       // per-half diagonal
__device__ float g_ymax[BB];
__device__ int   g_jmax[BB];

typedef unsigned long long ull;

__device__ __forceinline__ void fma2(ull& acc, ull a, ull b) {
    asm("fma.rn.f32x2 %0, %1, %2, %0;" : "+l"(acc) : "l"(a), "l"(b));
}
__device__ __forceinline__ float lo32(ull u) { return __uint_as_float((unsigned)u); }
__device__ __forceinline__ float hi32(ull u) { return __uint_as_float((unsigned)(u >> 32)); }

// ---------------------------------------------------------------------------
// K1 fused:
//   bid < 272            -> Gram 64x64 upper-tri tile, split-K half (FMA-bound)
//   272 <= bid < 272+BB  -> one y-row: argmax/max + copy into out (DRAM-bound)
// ---------------------------------------------------------------------------
#define NT 16
#define NPAIR (NT * (NT + 1) / 2)   // 136
#define NGRAM (2 * NPAIR)           // 272 (x2 split-K)
#define BK 32
#define KHALF (HH / 2)              // 256
#define NKS (KHALF / BK)            // 8
#define SROW 34                     // even stride; 34 mod 32 = 2 -> conflict-free

__global__ void __launch_bounds__(128)
k_main(const float* __restrict__ y,
       const float* __restrict__ w,
       float* __restrict__ out) {
    __shared__ float As[64 * SROW];
    __shared__ float Bs[64 * SROW];
    const int t = threadIdx.x;

    if (blockIdx.x >= NGRAM) {
        // ---------------- argmax + copy: one y-row per block ----------------
        // out rows stride 1001 floats: odd rows not 16B aligned -> scalar stores.
        const int b = blockIdx.x - NGRAM;
        const float4* yr = (const float4*)(y + (long)b * CC);
        float* orow = out + (long)b * (CC + 1);

        float vmax = NEG_INF; int imax = 0;
        #pragma unroll
        for (int r = 0; r < 2; r++) {
            const int i = t + 128 * r;
            if (i < CC / 4) {
                const float4 v = __ldg(&yr[i]);
                const int c = i * 4;
                orow[c] = v.x; orow[c + 1] = v.y; orow[c + 2] = v.z; orow[c + 3] = v.w;
                if (v.x > vmax) { vmax = v.x; imax = c; }
                if (v.y > vmax) { vmax = v.y; imax = c + 1; }
                if (v.z > vmax) { vmax = v.z; imax = c + 2; }
                if (v.w > vmax) { vmax = v.w; imax = c + 3; }
            }
        }
        const int lane = t & 31, wid = t >> 5;
        #pragma unroll
        for (int o = 16; o > 0; o >>= 1) {
            const float v2 = __shfl_xor_sync(0xffffffffu, vmax, o);
            const int   i2 = __shfl_xor_sync(0xffffffffu, imax, o);
            if (v2 > vmax || (v2 == vmax && i2 < imax)) { vmax = v2; imax = i2; }
        }
        float* swv = As;
        int*   swi = (int*)Bs;
        if (lane == 0) { swv[wid] = vmax; swi[wid] = imax; }
        __syncthreads();
        if (t == 0) {
            float bv = swv[0]; int bi = swi[0];
            #pragma unroll
            for (int k = 1; k < 4; k++) {
                if (swv[k] > bv || (swv[k] == bv && swi[k] < bi)) { bv = swv[k]; bi = swi[k]; }
            }
            g_ymax[b] = bv; g_jmax[b] = bi;
        }
        return;
    }

    // -------------------------- Gram tile (split-K) --------------------------
    const int kh = (blockIdx.x >= NPAIR) ? 1 : 0;
    int p = blockIdx.x - kh * NPAIR;
    int ti = 0;
    while (p >= NT - ti) { p -= NT - ti; ti++; }
    const int tj = ti + p;
    const int k0 = kh * KHALF;

    const int lrow = t >> 3;        // 0..15
    const int seg  = t & 7;         // 0..7
    const int tr8  = (t >> 4) * 8;  // 0..56
    const int tc   = t & 15;

    const float* pA[4];
    const float* pB[4];
    #pragma unroll
    for (int m = 0; m < 4; m++) {
        const int ra = min(ti * 64 + lrow + 16 * m, CC - 1);
        const int rb = min(tj * 64 + lrow + 16 * m, CC - 1);
        pA[m] = w + (long)ra * HH + k0 + seg * 4;
        pB[m] = w + (long)rb * HH + k0 + seg * 4;
    }

    ull acc[8][4];
    #pragma unroll
    for (int i = 0; i < 8; i++)
        #pragma unroll
        for (int g = 0; g < 4; g++) acc[i][g] = 0ull;

    float4 ra4[4], rb4[4];
    #pragma unroll
    for (int m = 0; m < 4; m++) {
        ra4[m] = *(const float4*)(pA[m]);
        rb4[m] = *(const float4*)(pB[m]);
    }

    #pragma unroll 1
    for (int ks = 0; ks < NKS; ks++) {
        __syncthreads();
        #pragma unroll
        for (int m = 0; m < 4; m++) {
            const int base = (lrow + 16 * m) * SROW + seg * 4;
            *(float2*)&As[base]     = make_float2(ra4[m].x, ra4[m].y);
            *(float2*)&As[base + 2] = make_float2(ra4[m].z, ra4[m].w);
            *(float2*)&Bs[base]     = make_float2(rb4[m].x, rb4[m].y);
            *(float2*)&Bs[base + 2] = make_float2(rb4[m].z, rb4[m].w);
        }
        __syncthreads();

        if (ks + 1 < NKS) {                    // prefetch next K-slab
            const int off = (ks + 1) * BK;
            #pragma unroll
            for (int m = 0; m < 4; m++) {
                ra4[m] = *(const float4*)(pA[m] + off);
                rb4[m] = *(const float4*)(pB[m] + off);
            }
        }

        #pragma unroll
        for (int kk = 0; kk < BK / 2; kk++) {
            ull a[8], b[4];
            #pragma unroll
            for (int i = 0; i < 8; i++)
                a[i] = *(const ull*)&As[(tr8 + i) * SROW + 2 * kk];
            #pragma unroll
            for (int g = 0; g < 4; g++)
                b[g] = *(const ull*)&Bs[(tc + 16 * g) * SROW + 2 * kk];
            #pragma unroll
            for (int i = 0; i < 8; i++)
                #pragma unroll
                for (int g = 0; g < 4; g++)
                    fma2(acc[i][g], a[i], b[g]);
        }
    }

    float res[8][4];
    #pragma unroll
    for (int i = 0; i < 8; i++)
        #pragma unroll
        for (int g = 0; g < 4; g++)
            res[i][g] = lo32(acc[i][g]) + hi32(acc[i][g]);

    float* G = &g_G2[kh][0];
    const int gr = ti * 64 + tr8;
    const int gc = tj * 64 + tc;
    #pragma unroll
    for (int i = 0; i < 8; i++)
        #pragma unroll
        for (int g = 0; g < 4; g++)
            G[(long)(gr + i) * 1024 + gc + 16 * g] = res[i][g];
    // mirror store; diagonal tiles double-write identical values (benign)
    #pragma unroll
    for (int g = 0; g < 4; g++) {
        const long mrow = (long)(gc + 16 * g) * 1024;
        float4 v0, v1;
        v0.x = res[0][g]; v0.y = res[1][g]; v0.z = res[2][g]; v0.w = res[3][g];
        v1.x = res[4][g]; v1.y = res[5][g]; v1.z = res[6][g]; v1.w = res[7][g];
        *(float4*)&G[mrow + gr]     = v0;
        *(float4*)&G[mrow + gr + 4] = v1;
    }
    if (ti == tj) {   // per-half diagonal -> norms
        #pragma unroll
        for (int i = 0; i < 8; i++)
            #pragma unroll
            for (int g = 0; g < 4; g++)
                if (tr8 + i == tc + 16 * g)
                    g_norm2[kh][ti * 64 + tr8 + i] = res[i][g];
    }
}

// ---------------------------------------------------------------------------
// K2: y_bot. 4 warps (128 threads) per row; <=2 float4-quads per thread,
// all loads batched, pruned sqrt, smem cross-warp reduce.
// ---------------------------------------------------------------------------
__global__ void __launch_bounds__(128)
k_bot(const float* __restrict__ y,
      const float* __restrict__ eps_p,
      const float* __restrict__ lip_p,
      float* __restrict__ out) {
    const int b = blockIdx.x;
    const int t = threadIdx.x;
    __shared__ float sred[4];

    const float s  = (*eps_p) * fabsf(*lip_p);
    const float s2 = s * s;

    const int   j    = g_jmax[b];
    const float ymax = g_ymax[b];
    const float nj   = g_norm2[0][j] + g_norm2[1][j];
    const float4* yr  = (const float4*)(y + (long)b * CC);
    const float4* g0r = (const float4*)(&g_G2[0][0] + (long)j * 1024);
    const float4* g1r = (const float4*)(&g_G2[1][0] + (long)j * 1024);
    const float4* n0r = (const float4*)&g_norm2[0][0];
    const float4* n1r = (const float4*)&g_norm2[1][0];

    // batch all loads (i0 = t always < 250; i1 = t+128 valid for t < 122)
    const int i0 = t, i1 = t + 128;
    const bool v1 = (i1 < CC / 4);
    float4 vy0 = __ldg(&yr[i0]);
    float4 vg0 = g0r[i0]; float4 vh0 = g1r[i0];
    float4 vn0 = n0r[i0]; float4 vm0 = n1r[i0];
    float4 vy1, vg1, vh1, vn1, vm1;
    if (v1) {
        vy1 = __ldg(&yr[i1]);
        vg1 = g0r[i1]; vh1 = g1r[i1];
        vn1 = n0r[i1]; vm1 = n1r[i1];
    }

    float best = NEG_INF;
    #pragma unroll
    for (int q = 0; q < 2; q++) {
        if (q == 1 && !v1) break;
        const float4 yv = q ? vy1 : vy0;
        const float4 gv = q ? vg1 : vg0;
        const float4 hv = q ? vh1 : vh0;
        const float4 nv = q ? vn1 : vn0;
        const float4 mv = q ? vm1 : vm0;
        #pragma unroll
        for (int e = 0; e < 4; e++) {
            const float yve = (e == 0) ? yv.x : (e == 1) ? yv.y : (e == 2) ? yv.z : yv.w;
            const float dot = ((e == 0) ? gv.x : (e == 1) ? gv.y : (e == 2) ? gv.z : gv.w)
                            + ((e == 0) ? hv.x : (e == 1) ? hv.y : (e == 2) ? hv.z : hv.w);
            const float nc  = ((e == 0) ? nv.x : (e == 1) ? nv.y : (e == 2) ? nv.z : nv.w)
                            + ((e == 0) ? mv.x : (e == 1) ? mv.y : (e == 2) ? mv.z : mv.w);
            if (yve == ymax) continue;           // ref masks y==ymax -> -inf
            float sq = fmaf(-2.f, dot, nj + nc);
            if (sq < 0.f) sq = 0.f;
            const float d = best - yve;
            if (d <= 0.f || sq * s2 > d * d) {
                best = fmaxf(best, fmaf(s, sqrtf(sq), yve));
            }
        }
    }
    const int lane = t & 31, wid = t >> 5;
    #pragma unroll
    for (int o = 16; o > 0; o >>= 1)
        best = fmaxf(best, __shfl_xor_sync(0xffffffffu, best, o));
    if (lane == 0) sred[wid] = best;
    __syncthreads();
    if (t == 0) {
        float r = fmaxf(fmaxf(sred[0], sred[1]), fmaxf(sred[2], sred[3]));
        out[(long)b * (CC + 1) + CC] = r;
    }
}

// ---------------------------------------------------------------------------
extern "C" void kernel_launch(void* const* d_in, const int* in_sizes, int n_in,
                              void* d_out, int out_size) {
    const float* y   = (const float*)d_in[0];
    const float* w   = (const float*)d_in[1];
    const float* eps = (const float*)d_in[2];
    const float* lip = (const float*)d_in[3];
    float* out = (float*)d_out;

    k_main<<<NGRAM + BB, 128>>>(y, w, out);
    k_bot<<<BB, 128>>>(y, eps, lip, out);
}

// round 7
// speedup vs baseline: 1.5696x; 1.2443x over previous
#include <cuda_runtime.h>
#include <cuda_bf16.h>
#include <mma.h>
#include <cstdint>

using namespace nvcuda;

#define BB 1024
#define CC 1000
#define HH 512
#define NEG_INF (__int_as_float(0xff800000))

// ---------------- scratch (__device__ globals; no allocs) ----------------
__device__ __nv_bfloat16 g_whi[1024 * 512];   // bf16 high part (rows >= 1000 zero)
__device__ __nv_bfloat16 g_wlo[1024 * 512];   // bf16 residual
__device__ float g_G[1024 * 1024];            // full symmetric Gram (fp32)
__device__ float g_norm[1024];                // exact fp32 row norms

// ---------------------------------------------------------------------------
// k_conv: w (f32 [1000,512]) -> g_whi/g_wlo bf16 [1024,512] (zero-padded) +
//         exact f32 norms. grid=1024 blocks, 128 threads, 4 elems/thread.
// ---------------------------------------------------------------------------
__global__ void __launch_bounds__(128)
k_conv(const float* __restrict__ w) {
    const int row = blockIdx.x;
    const int t = threadIdx.x;
    __shared__ float sred[4];

    uint64_t packhi = 0, packlo = 0;
    float nacc = 0.f;
    if (row < CC) {
        const float4 v = __ldg((const float4*)(w + (long)row * HH) + t);
        const float e[4] = {v.x, v.y, v.z, v.w};
        #pragma unroll
        for (int i = 0; i < 4; i++) {
            const __nv_bfloat16 h = __float2bfloat16(e[i]);
            const __nv_bfloat16 l = __float2bfloat16(e[i] - __bfloat162float(h));
            packhi |= (uint64_t)__bfloat16_as_ushort(h) << (16 * i);
            packlo |= (uint64_t)__bfloat16_as_ushort(l) << (16 * i);
            nacc = fmaf(e[i], e[i], nacc);
        }
    }
    *(uint64_t*)&g_whi[(long)row * HH + 4 * t] = packhi;
    *(uint64_t*)&g_wlo[(long)row * HH + 4 * t] = packlo;

    #pragma unroll
    for (int o = 16; o > 0; o >>= 1)
        nacc += __shfl_xor_sync(0xffffffffu, nacc, o);
    if ((t & 31) == 0) sred[t >> 5] = nacc;
    __syncthreads();
    if (t == 0) g_norm[row] = sred[0] + sred[1] + sred[2] + sred[3];
}

// ---------------------------------------------------------------------------
// k_gram: bf16-split Gram on the tensor pipe via wmma (HMMA.16816 — works on
// base sm_103 target; tcgen05 needs the 'a' suffix this harness doesn't emit).
// 136 CTAs = 16x16 upper-tri of 64x64 tiles; 128 thr; warp tile 32x32.
// G = hi*hi^T + hi*lo^T + lo*hi^T (lo*lo dropped, ~1e-5 rel).
// ---------------------------------------------------------------------------
#define NTT 16
#define NPAIR (NTT * (NTT + 1) / 2)   // 136
#define BKC 32
#define NKS (HH / BKC)                // 16
#define SST 40                        // smem stride (bf16 elems): 80B rows,
                                      // 16B-aligned, conflict-free ldsm phases
#define OPB (64 * SST)                // elems per operand buffer (2560)

__global__ void __launch_bounds__(128)
k_gram() {
    // union: 4 bf16 operand buffers (20KB) / fp32 epilogue tile (17.4KB)
    __shared__ __align__(16) char smem_raw[4 * OPB * 2];
    __nv_bfloat16* sAhi = (__nv_bfloat16*)smem_raw;
    __nv_bfloat16* sAlo = sAhi + OPB;
    __nv_bfloat16* sBhi = sAlo + OPB;
    __nv_bfloat16* sBlo = sBhi + OPB;
    float* Cs = (float*)smem_raw;     // stride 68 in epilogue

    const int t = threadIdx.x;
    const int warp = t >> 5;
    const int wr = (warp >> 1) * 32;  // warp row base in tile
    const int wc = (warp & 1) * 32;   // warp col base in tile

    int p = blockIdx.x, ti = 0;
    while (p >= NTT - ti) { p -= NTT - ti; ti++; }
    const int tj = ti + p;

    // loader mapping: row = t>>1 (0..63), half = t&1 -> two uint4 (16 bf16)
    const int lrow = t >> 1;
    const int lseg = (t & 1) * 16;
    const long abase = (long)(ti * 64 + lrow) * HH + lseg;
    const long bbase = (long)(tj * 64 + lrow) * HH + lseg;
    const int sbase = lrow * SST + lseg;

    wmma::fragment<wmma::accumulator, 16, 16, 16, float> acc[2][2];
    #pragma unroll
    for (int i = 0; i < 2; i++)
        #pragma unroll
        for (int j = 0; j < 2; j++) wmma::fill_fragment(acc[i][j], 0.f);

    uint4 pf[8];
    {   // prefetch chunk 0
        pf[0] = *(const uint4*)(g_whi + abase);
        pf[1] = *(const uint4*)(g_whi + abase + 8);
        pf[2] = *(const uint4*)(g_wlo + abase);
        pf[3] = *(const uint4*)(g_wlo + abase + 8);
        pf[4] = *(const uint4*)(g_whi + bbase);
        pf[5] = *(const uint4*)(g_whi + bbase + 8);
        pf[6] = *(const uint4*)(g_wlo + bbase);
        pf[7] = *(const uint4*)(g_wlo + bbase + 8);
    }

    #pragma unroll 1
    for (int ks = 0; ks < NKS; ks++) {
        __syncthreads();   // previous chunk fully consumed
        *(uint4*)(sAhi + sbase)     = pf[0];
        *(uint4*)(sAhi + sbase + 8) = pf[1];
        *(uint4*)(sAlo + sbase)     = pf[2];
        *(uint4*)(sAlo + sbase + 8) = pf[3];
        *(uint4*)(sBhi + sbase)     = pf[4];
        *(uint4*)(sBhi + sbase + 8) = pf[5];
        *(uint4*)(sBlo + sbase)     = pf[6];
        *(uint4*)(sBlo + sbase + 8) = pf[7];
        __syncthreads();

        if (ks + 1 < NKS) {   // prefetch next chunk (overlaps MMA)
            const long ao = abase + (ks + 1) * BKC;
            const long bo = bbase + (ks + 1) * BKC;
            pf[0] = *(const uint4*)(g_whi + ao);
            pf[1] = *(const uint4*)(g_whi + ao + 8);
            pf[2] = *(const uint4*)(g_wlo + ao);
            pf[3] = *(const uint4*)(g_wlo + ao + 8);
            pf[4] = *(const uint4*)(g_whi + bo);
            pf[5] = *(const uint4*)(g_whi + bo + 8);
            pf[6] = *(const uint4*)(g_wlo + bo);
            pf[7] = *(const uint4*)(g_wlo + bo + 8);
        }

        #pragma unroll
        for (int kk = 0; kk < BKC; kk += 16) {
            wmma::fragment<wmma::matrix_a, 16, 16, 16, __nv_bfloat16, wmma::row_major> ah[2], al[2];
            wmma::fragment<wmma::matrix_b, 16, 16, 16, __nv_bfloat16, wmma::col_major> bh[2], bl[2];
            #pragma unroll
            for (int i = 0; i < 2; i++) {
                wmma::load_matrix_sync(ah[i], sAhi + (wr + 16 * i) * SST + kk, SST);
                wmma::load_matrix_sync(al[i], sAlo + (wr + 16 * i) * SST + kk, SST);
                wmma::load_matrix_sync(bh[i], sBhi + (wc + 16 * i) * SST + kk, SST);
                wmma::load_matrix_sync(bl[i], sBlo + (wc + 16 * i) * SST + kk, SST);
            }
            #pragma unroll
            for (int i = 0; i < 2; i++)
                #pragma unroll
                for (int j = 0; j < 2; j++) {
                    wmma::mma_sync(acc[i][j], ah[i], bh[j], acc[i][j]);
                    wmma::mma_sync(acc[i][j], ah[i], bl[j], acc[i][j]);
                    wmma::mma_sync(acc[i][j], al[i], bh[j], acc[i][j]);
                }
        }
    }

    // ---------------- epilogue via smem, then coalesced global ----------------
    __syncthreads();   // done with bf16 buffers; reuse as float Cs[64][68]
    #pragma unroll
    for (int i = 0; i < 2; i++)
        #pragma unroll
        for (int j = 0; j < 2; j++)
            wmma::store_matrix_sync(Cs + (wr + 16 * i) * 68 + wc + 16 * j,
                                    acc[i][j], 68, wmma::mem_row_major);
    __syncthreads();

    // upper tile: 64 rows x 16 float4
    for (int idx = t; idx < 64 * 16; idx += 128) {
        const int r = idx >> 4, c4 = idx & 15;
        const float4 v = *(const float4*)(Cs + r * 68 + c4 * 4);
        *(float4*)&g_G[(long)(ti * 64 + r) * 1024 + tj * 64 + c4 * 4] = v;
    }
    // mirror tile (transposed); diagonal tiles rewrite identical values
    for (int idx = t; idx < 64 * 16; idx += 128) {
        const int c = idx >> 4, r4 = idx & 15;
        float4 v;
        v.x = Cs[(4 * r4 + 0) * 68 + c];
        v.y = Cs[(4 * r4 + 1) * 68 + c];
        v.z = Cs[(4 * r4 + 2) * 68 + c];
        v.w = Cs[(4 * r4 + 3) * 68 + c];
        *(float4*)&g_G[(long)(tj * 64 + c) * 1024 + ti * 64 + 4 * r4] = v;
    }
}

// ---------------------------------------------------------------------------
// k_bot: per-row fused argmax + copy + y_bot. 1024 blocks x 256 threads.
// ---------------------------------------------------------------------------
__global__ void __launch_bounds__(256)
k_bot(const float* __restrict__ y,
      const float* __restrict__ eps_p,
      const float* __restrict__ lip_p,
      float* __restrict__ out) {
    const int b = blockIdx.x;
    const int t = threadIdx.x;
    const int lane = t & 31, wid = t >> 5;
    __shared__ float sv[8];
    __shared__ int   si[8];
    __shared__ float sm[8];
    __shared__ float s_ymax;
    __shared__ int   s_j;

    const float4* yr = (const float4*)(y + (long)b * CC);
    float* orow = out + (long)b * (CC + 1);

    // ---- load y, copy, block argmax (first-index tie-break) ----
    float4 vy = make_float4(NEG_INF, NEG_INF, NEG_INF, NEG_INF);
    float vmax = NEG_INF; int imax = 0x7fffffff;
    if (t < CC / 4) {
        vy = __ldg(&yr[t]);
        const int c = t * 4;
        orow[c] = vy.x; orow[c + 1] = vy.y; orow[c + 2] = vy.z; orow[c + 3] = vy.w;
        vmax = vy.x; imax = c;
        if (vy.y > vmax) { vmax = vy.y; imax = c + 1; }
        if (vy.z > vmax) { vmax = vy.z; imax = c + 2; }
        if (vy.w > vmax) { vmax = vy.w; imax = c + 3; }
    }
    #pragma unroll
    for (int o = 16; o > 0; o >>= 1) {
        const float v2 = __shfl_xor_sync(0xffffffffu, vmax, o);
        const int   i2 = __shfl_xor_sync(0xffffffffu, imax, o);
        if (v2 > vmax || (v2 == vmax && i2 < imax)) { vmax = v2; imax = i2; }
    }
    if (lane == 0) { sv[wid] = vmax; si[wid] = imax; }
    __syncthreads();
    if (t == 0) {
        float bv = sv[0]; int bi = si[0];
        #pragma unroll
        for (int k = 1; k < 8; k++)
            if (sv[k] > bv || (sv[k] == bv && si[k] < bi)) { bv = sv[k]; bi = si[k]; }
        s_ymax = bv; s_j = bi;
    }
    __syncthreads();
    const float ymax = s_ymax;
    const int j = s_j;

    // ---- y_bot with pruned sqrt ----
    const float s  = (*eps_p) * fabsf(*lip_p);
    const float s2 = s * s;
    const float nj = g_norm[j];

    float best = NEG_INF;
    if (t < CC / 4) {
        const float4 gv = *((const float4*)(g_G + (long)j * 1024) + t);
        const float4 nv = *((const float4*)g_norm + t);
        const float ye[4] = {vy.x, vy.y, vy.z, vy.w};
        const float ge[4] = {gv.x, gv.y, gv.z, gv.w};
        const float ne[4] = {nv.x, nv.y, nv.z, nv.w};
        #pragma unroll
        for (int e = 0; e < 4; e++) {
            if (ye[e] == ymax) continue;        // ref masks y==ymax -> -inf
            float sq = fmaf(-2.f, ge[e], nj + ne[e]);
            if (sq < 0.f) sq = 0.f;
            const float d = best - ye[e];
            if (d <= 0.f || sq * s2 > d * d)
                best = fmaxf(best, fmaf(s, sqrtf(sq), ye[e]));
        }
    }
    #pragma unroll
    for (int o = 16; o > 0; o >>= 1)
        best = fmaxf(best, __shfl_xor_sync(0xffffffffu, best, o));
    if (lane == 0) sm[wid] = best;
    __syncthreads();
    if (t == 0) {
        float r = sm[0];
        #pragma unroll
        for (int k = 1; k < 8; k++) r = fmaxf(r, sm[k]);
        orow[CC] = r;
    }
}

// ---------------------------------------------------------------------------
extern "C" void kernel_launch(void* const* d_in, const int* in_sizes, int n_in,
                              void* d_out, int out_size) {
    const float* y   = (const float*)d_in[0];
    const float* w   = (const float*)d_in[1];
    const float* eps = (const float*)d_in[2];
    const float* lip = (const float*)d_in[3];
    float* out = (float*)d_out;

    k_conv<<<1024, 128>>>(w);
    k_gram<<<NPAIR, 128>>>();
    k_bot<<<BB, 256>>>(y, eps, lip, out);
}

// round 8
// speedup vs baseline: 1.7246x; 1.0987x over previous
#include <cuda_runtime.h>
#include <cuda_bf16.h>
#include <mma.h>
#include <cstdint>

using namespace nvcuda;

#define BB 1024
#define CC 1000
#define HH 512
#define NEG_INF (__int_as_float(0xff800000))

// ---------------- scratch (__device__ globals; zero-initialized) ----------------
__device__ __nv_bfloat16 g_whi[1024 * 512];   // bf16 high part (rows >=1000 stay zero)
__device__ __nv_bfloat16 g_wlo[1024 * 512];   // bf16 residual
__device__ float g_G[1024 * 1024];            // full symmetric Gram (fp32)
__device__ float g_norm[1024];                // exact fp32 row norms

// ---------------- cp.async helpers (sm_80+ ISA, base-target safe) ----------------
__device__ __forceinline__ uint32_t smem_u32(const void* p) {
    return (uint32_t)__cvta_generic_to_shared(p);
}
__device__ __forceinline__ void cp16(uint32_t dst, const void* src) {
    asm volatile("cp.async.cg.shared.global [%0], [%1], 16;" :: "r"(dst), "l"(src));
}
__device__ __forceinline__ void cp_commit() {
    asm volatile("cp.async.commit_group;" ::: "memory");
}
template <int N>
__device__ __forceinline__ void cp_wait() {
    asm volatile("cp.async.wait_group %0;" :: "n"(N) : "memory");
}

// ---------------------------------------------------------------------------
// k_conv: w f32 [1000,512] -> g_whi/g_wlo bf16 + exact norms.
// 250 blocks x 512 threads; 4 rows/block, 1 float4/thread.
// ---------------------------------------------------------------------------
__global__ void __launch_bounds__(512)
k_conv(const float* __restrict__ w) {
    const int t = threadIdx.x;
    const int rloc = t >> 7;                 // 0..3  (row within block)
    const int q = t & 127;                   // 0..127 (float4 within row)
    const int row = blockIdx.x * 4 + rloc;   // < 1000 exactly
    __shared__ float sred[16];

    const float4 v = __ldg((const float4*)(w + (long)row * HH) + q);
    const float e[4] = {v.x, v.y, v.z, v.w};
    uint64_t packhi = 0, packlo = 0;
    float nacc = 0.f;
    #pragma unroll
    for (int i = 0; i < 4; i++) {
        const __nv_bfloat16 h = __float2bfloat16(e[i]);
        const __nv_bfloat16 l = __float2bfloat16(e[i] - __bfloat162float(h));
        packhi |= (uint64_t)__bfloat16_as_ushort(h) << (16 * i);
        packlo |= (uint64_t)__bfloat16_as_ushort(l) << (16 * i);
        nacc = fmaf(e[i], e[i], nacc);
    }
    *(uint64_t*)&g_whi[(long)row * HH + 4 * q] = packhi;
    *(uint64_t*)&g_wlo[(long)row * HH + 4 * q] = packlo;

    #pragma unroll
    for (int o = 16; o > 0; o >>= 1)
        nacc += __shfl_xor_sync(0xffffffffu, nacc, o);
    if ((t & 31) == 0) sred[t >> 5] = nacc;
    __syncthreads();
    if (q == 0)
        g_norm[row] = sred[4 * rloc] + sred[4 * rloc + 1]
                    + sred[4 * rloc + 2] + sred[4 * rloc + 3];
}

// ---------------------------------------------------------------------------
// k_gram: bf16-split Gram on tensor pipe (wmma/HMMA). 136 CTAs (16x16 upper
// tri of 64x64 tiles), 128 thr, warp tile 32x32.
// G = hi*hi^T + hi*lo^T + lo*hi^T. cp.async double-buffered K-chunks of 32.
// ---------------------------------------------------------------------------
#define NTT 16
#define NPAIR (NTT * (NTT + 1) / 2)   // 136
#define BKC 32
#define NKS (HH / BKC)                // 16
#define SST 40                        // smem stride (bf16): 80B rows; ldsm
                                      // phases hit banks 20r mod 32 - distinct
#define OPBYTES (64 * SST * 2)        // 5120 B per operand buffer

__global__ void __launch_bounds__(128)
k_gram() {
    // 2 stages x 4 operands x 5120B = 40KB; epilogue reuses as float[64][68]
    __shared__ __align__(16) char smem_raw[2 * 4 * OPBYTES];
    float* Cs = (float*)smem_raw;

    const int t = threadIdx.x;
    const int warp = t >> 5;
    const int wr = (warp >> 1) * 32;
    const int wc = (warp & 1) * 32;

    int p = blockIdx.x, ti = 0;
    while (p >= NTT - ti) { p -= NTT - ti; ti++; }
    const int tj = ti + p;

    // loader: lrow = t>>1 (0..63), lh = t&1 -> 16 bf16 (32B) per operand
    const int lrow = t >> 1;
    const int lh = t & 1;
    const long aoff = (long)(ti * 64 + lrow) * HH + lh * 16;
    const long boff = (long)(tj * 64 + lrow) * HH + lh * 16;
    const uint32_t sdst = smem_u32(smem_raw) + lrow * (SST * 2) + lh * 32;

    const __nv_bfloat16* gsrc[4] = {g_whi, g_wlo, g_whi, g_wlo}; // Ahi Alo Bhi Blo

    auto issue = [&](int chunk, int buf) {
        const long co = (long)chunk * BKC;
        #pragma unroll
        for (int op = 0; op < 4; op++) {
            const __nv_bfloat16* src = gsrc[op] + ((op < 2) ? aoff : boff) + co;
            const uint32_t dst = sdst + (buf * 4 + op) * OPBYTES;
            cp16(dst, src);
            cp16(dst + 16, src + 8);
        }
    };

    wmma::fragment<wmma::accumulator, 16, 16, 16, float> acc[2][2];
    #pragma unroll
    for (int i = 0; i < 2; i++)
        #pragma unroll
        for (int j = 0; j < 2; j++) wmma::fill_fragment(acc[i][j], 0.f);

    issue(0, 0); cp_commit();
    issue(1, 1); cp_commit();

    #pragma unroll 1
    for (int ks = 0; ks < NKS; ks++) {
        const int buf = ks & 1;
        cp_wait<1>();          // chunk ks resident
        __syncthreads();

        const __nv_bfloat16* sAhi = (const __nv_bfloat16*)(smem_raw + (buf * 4 + 0) * OPBYTES);
        const __nv_bfloat16* sAlo = (const __nv_bfloat16*)(smem_raw + (buf * 4 + 1) * OPBYTES);
        const __nv_bfloat16* sBhi = (const __nv_bfloat16*)(smem_raw + (buf * 4 + 2) * OPBYTES);
        const __nv_bfloat16* sBlo = (const __nv_bfloat16*)(smem_raw + (buf * 4 + 3) * OPBYTES);

        #pragma unroll
        for (int kk = 0; kk < BKC; kk += 16) {
            wmma::fragment<wmma::matrix_a, 16, 16, 16, __nv_bfloat16, wmma::row_major> ah[2], al[2];
            wmma::fragment<wmma::matrix_b, 16, 16, 16, __nv_bfloat16, wmma::col_major> bh[2], bl[2];
            #pragma unroll
            for (int i = 0; i < 2; i++) {
                wmma::load_matrix_sync(ah[i], sAhi + (wr + 16 * i) * SST + kk, SST);
                wmma::load_matrix_sync(al[i], sAlo + (wr + 16 * i) * SST + kk, SST);
                wmma::load_matrix_sync(bh[i], sBhi + (wc + 16 * i) * SST + kk, SST);
                wmma::load_matrix_sync(bl[i], sBlo + (wc + 16 * i) * SST + kk, SST);
            }
            #pragma unroll
            for (int i = 0; i < 2; i++)
                #pragma unroll
                for (int j = 0; j < 2; j++) {
                    wmma::mma_sync(acc[i][j], ah[i], bh[j], acc[i][j]);
                    wmma::mma_sync(acc[i][j], ah[i], bl[j], acc[i][j]);
                    wmma::mma_sync(acc[i][j], al[i], bh[j], acc[i][j]);
                }
        }
        __syncthreads();       // all warps done reading buf before overwrite

        if (ks + 2 < NKS) issue(ks + 2, buf);
        cp_commit();           // empty group when nothing issued: keeps counts
    }

    // ---------------- epilogue (reuse smem as float Cs[64][68]) ----------------
    #pragma unroll
    for (int i = 0; i < 2; i++)
        #pragma unroll
        for (int j = 0; j < 2; j++)
            wmma::store_matrix_sync(Cs + (wr + 16 * i) * 68 + wc + 16 * j,
                                    acc[i][j], 68, wmma::mem_row_major);
    __syncthreads();

    for (int idx = t; idx < 64 * 16; idx += 128) {      // upper tile
        const int r = idx >> 4, c4 = idx & 15;
        const float4 v = *(const float4*)(Cs + r * 68 + c4 * 4);
        *(float4*)&g_G[(long)(ti * 64 + r) * 1024 + tj * 64 + c4 * 4] = v;
    }
    for (int idx = t; idx < 64 * 16; idx += 128) {      // mirror (transposed)
        const int c = idx >> 4, r4 = idx & 15;
        float4 v;
        v.x = Cs[(4 * r4 + 0) * 68 + c];
        v.y = Cs[(4 * r4 + 1) * 68 + c];
        v.z = Cs[(4 * r4 + 2) * 68 + c];
        v.w = Cs[(4 * r4 + 3) * 68 + c];
        *(float4*)&g_G[(long)(tj * 64 + c) * 1024 + ti * 64 + 4 * r4] = v;
    }
}

// ---------------------------------------------------------------------------
// k_bot: per-row fused argmax + copy + y_bot. 1024 blocks x 256 threads.
// ---------------------------------------------------------------------------
__global__ void __launch_bounds__(256)
k_bot(const float* __restrict__ y,
      const float* __restrict__ eps_p,
      const float* __restrict__ lip_p,
      float* __restrict__ out) {
    const int b = blockIdx.x;
    const int t = threadIdx.x;
    const int lane = t & 31, wid = t >> 5;
    __shared__ float sv[8];
    __shared__ int   si[8];
    __shared__ float sm[8];
    __shared__ float s_ymax;
    __shared__ int   s_j;

    const float4* yr = (const float4*)(y + (long)b * CC);
    float* orow = out + (long)b * (CC + 1);

    float4 vy = make_float4(NEG_INF, NEG_INF, NEG_INF, NEG_INF);
    float vmax = NEG_INF; int imax = 0x7fffffff;
    if (t < CC / 4) {
        vy = __ldg(&yr[t]);
        const int c = t * 4;
        orow[c] = vy.x; orow[c + 1] = vy.y; orow[c + 2] = vy.z; orow[c + 3] = vy.w;
        vmax = vy.x; imax = c;
        if (vy.y > vmax) { vmax = vy.y; imax = c + 1; }
        if (vy.z > vmax) { vmax = vy.z; imax = c + 2; }
        if (vy.w > vmax) { vmax = vy.w; imax = c + 3; }
    }
    #pragma unroll
    for (int o = 16; o > 0; o >>= 1) {
        const float v2 = __shfl_xor_sync(0xffffffffu, vmax, o);
        const int   i2 = __shfl_xor_sync(0xffffffffu, imax, o);
        if (v2 > vmax || (v2 == vmax && i2 < imax)) { vmax = v2; imax = i2; }
    }
    if (lane == 0) { sv[wid] = vmax; si[wid] = imax; }
    __syncthreads();
    if (t == 0) {
        float bv = sv[0]; int bi = si[0];
        #pragma unroll
        for (int k = 1; k < 8; k++)
            if (sv[k] > bv || (sv[k] == bv && si[k] < bi)) { bv = sv[k]; bi = si[k]; }
        s_ymax = bv; s_j = bi;
    }
    __syncthreads();
    const float ymax = s_ymax;
    const int j = s_j;

    const float s  = (*eps_p) * fabsf(*lip_p);
    const float s2 = s * s;
    const float nj = g_norm[j];

    float best = NEG_INF;
    if (t < CC / 4) {
        const float4 gv = *((const float4*)(g_G + (long)j * 1024) + t);
        const float4 nv = *((const float4*)g_norm + t);
        const float ye[4] = {vy.x, vy.y, vy.z, vy.w};
        const float ge[4] = {gv.x, gv.y, gv.z, gv.w};
        const float ne[4] = {nv.x, nv.y, nv.z, nv.w};
        #pragma unroll
        for (int e = 0; e < 4; e++) {
            if (ye[e] == ymax) continue;        // ref masks y==ymax -> -inf
            float sq = fmaf(-2.f, ge[e], nj + ne[e]);
            if (sq < 0.f) sq = 0.f;
            const float d = best - ye[e];
            if (d <= 0.f || sq * s2 > d * d)
                best = fmaxf(best, fmaf(s, sqrtf(sq), ye[e]));
        }
    }
    #pragma unroll
    for (int o = 16; o > 0; o >>= 1)
        best = fmaxf(best, __shfl_xor_sync(0xffffffffu, best, o));
    if (lane == 0) sm[wid] = best;
    __syncthreads();
    if (t == 0) {
        float r = sm[0];
        #pragma unroll
        for (int k = 1; k < 8; k++) r = fmaxf(r, sm[k]);
        orow[CC] = r;
    }
}

// ---------------------------------------------------------------------------
extern "C" void kernel_launch(void* const* d_in, const int* in_sizes, int n_in,
                              void* d_out, int out_size) {
    const float* y   = (const float*)d_in[0];
    const float* w   = (const float*)d_in[1];
    const float* eps = (const float*)d_in[2];
    const float* lip = (const float*)d_in[3];
    float* out = (float*)d_out;

    k_conv<<<250, 512>>>(w);
    k_gram<<<NPAIR, 128>>>();
    k_bot<<<BB, 256>>>(y, eps, lip, out);
}